// round 1
// baseline (speedup 1.0000x reference)
#include <cuda_runtime.h>
#include <math.h>

// Problem constants
#define Bsz   32768
#define Tt    7
#define Ff    36
#define Uu    256
#define Gg    1024   // 4*U
#define BM    32     // batch rows per CTA
#define NTHREADS 256

// ---------------------------------------------------------------------------
// f32x2 packed-FMA helpers (Blackwell sm_103a; ptxas will not auto-fuse FFMA2)
// ---------------------------------------------------------------------------
__device__ __forceinline__ unsigned long long pack2(float v) {
    unsigned long long r;
    asm("mov.b64 %0, {%1, %1};" : "=l"(r) : "f"(v));
    return r;
}
__device__ __forceinline__ void unpack2(unsigned long long v, float& lo, float& hi) {
    asm("mov.b64 {%0, %1}, %2;" : "=f"(lo), "=f"(hi) : "l"(v));
}
__device__ __forceinline__ void ffma2(unsigned long long& d,
                                      unsigned long long a,
                                      unsigned long long b) {
    asm("fma.rn.f32x2 %0, %1, %2, %0;" : "+l"(d) : "l"(a), "l"(b));
}
__device__ __forceinline__ float sigmoidf_(float z) {
    return 1.0f / (1.0f + expf(-z));
}

// ---------------------------------------------------------------------------
// One gate pass: acc[r][p] (float2 packed) = b[gate cols] + h@Wr + x_t@Wk
// Thread covers rows rbase..rbase+3 and 4 float2 column-pairs
// (float2 col index = cb + 32*p, i.e. units 2*(cb+32p)+{0,1}).
// ---------------------------------------------------------------------------
__device__ __forceinline__ void gate_pass(
    int cb,            // float2 column base within the 512-wide float2 row
    int t, int rbase,
    const unsigned long long* __restrict__ Wr2,
    const unsigned long long* __restrict__ Wk2,
    const unsigned long long* __restrict__ b2,
    const float (*h_sh)[Uu],
    const float (*x_sh)[Tt * Ff],
    unsigned long long acc[4][4])
{
    unsigned long long bias[4];
#pragma unroll
    for (int p = 0; p < 4; p++) bias[p] = b2[cb + 32 * p];
#pragma unroll
    for (int r = 0; r < 4; r++)
#pragma unroll
        for (int p = 0; p < 4; p++) acc[r][p] = bias[p];

    // ---- recurrent term: K = 256 over h ----
    const unsigned long long* wp = Wr2 + cb;
#pragma unroll 4
    for (int k = 0; k < Uu; k++) {
        unsigned long long w0 = wp[k * 512 + 0];
        unsigned long long w1 = wp[k * 512 + 32];
        unsigned long long w2 = wp[k * 512 + 64];
        unsigned long long w3 = wp[k * 512 + 96];
#pragma unroll
        for (int r = 0; r < 4; r++) {
            unsigned long long hv = pack2(h_sh[rbase + r][k]);
            ffma2(acc[r][0], hv, w0);
            ffma2(acc[r][1], hv, w1);
            ffma2(acc[r][2], hv, w2);
            ffma2(acc[r][3], hv, w3);
        }
    }

    // ---- input term: K = 36 over x_t ----
    const unsigned long long* kp = Wk2 + cb;
#pragma unroll 4
    for (int f = 0; f < Ff; f++) {
        unsigned long long w0 = kp[f * 512 + 0];
        unsigned long long w1 = kp[f * 512 + 32];
        unsigned long long w2 = kp[f * 512 + 64];
        unsigned long long w3 = kp[f * 512 + 96];
#pragma unroll
        for (int r = 0; r < 4; r++) {
            unsigned long long xv = pack2(x_sh[rbase + r][t * Ff + f]);
            ffma2(acc[r][0], xv, w0);
            ffma2(acc[r][1], xv, w1);
            ffma2(acc[r][2], xv, w2);
            ffma2(acc[r][3], xv, w3);
        }
    }
}

// ---------------------------------------------------------------------------
// LSTM kernel: one CTA = 32 batch rows, full 7-step recurrence in-block.
// ---------------------------------------------------------------------------
__global__ void __launch_bounds__(NTHREADS, 1)
lstm_kernel(const float* __restrict__ x,   // [B,T,F]
            const float* __restrict__ h0,  // [B,U]
            const float* __restrict__ c0,  // [B,U]
            const float* __restrict__ Wk,  // [F,4U]
            const float* __restrict__ Wr,  // [U,4U]
            const float* __restrict__ b,   // [4U]
            float* __restrict__ out)       // [B,T,U]
{
    __shared__ float h_sh[BM][Uu];        // 32 KB
    __shared__ float x_sh[BM][Tt * Ff];   // ~31.5 KB

    const int tid   = threadIdx.x;
    const int tu    = tid & 31;   // column lane (32 lanes over 128 float2 cols/gate)
    const int tb    = tid >> 5;   // row group 0..7
    const int rbase = tb * 4;
    const int row0  = blockIdx.x * BM;

    // Stage h0 into shared
    for (int i = tid; i < BM * Uu; i += NTHREADS) {
        int r = i >> 8, u = i & 255;
        h_sh[r][u] = h0[(row0 + r) * Uu + u];
    }
    // Stage x tile (all 7 steps) into shared
    for (int i = tid; i < BM * Tt * Ff; i += NTHREADS) {
        int r = i / (Tt * Ff), c = i % (Tt * Ff);
        x_sh[r][c] = x[(size_t)(row0 + r) * (Tt * Ff) + c];
    }

    // c lives in registers: creg[r][2p+e] <-> unit 2*(tu+32p)+e
    const unsigned long long* __restrict__ c02 =
        reinterpret_cast<const unsigned long long*>(c0);
    float creg[4][8];
#pragma unroll
    for (int r = 0; r < 4; r++)
#pragma unroll
        for (int p = 0; p < 4; p++) {
            unsigned long long cv = c02[(size_t)(row0 + rbase + r) * 128 + tu + 32 * p];
            unpack2(cv, creg[r][2 * p], creg[r][2 * p + 1]);
        }
    __syncthreads();

    const unsigned long long* __restrict__ Wr2 =
        reinterpret_cast<const unsigned long long*>(Wr);
    const unsigned long long* __restrict__ Wk2 =
        reinterpret_cast<const unsigned long long*>(Wk);
    const unsigned long long* __restrict__ b2 =
        reinterpret_cast<const unsigned long long*>(b);
    float2* __restrict__ out2 = reinterpret_cast<float2*>(out);

    float gv[4][8];                 // scratch: I, then P = i*g, then h_new
    unsigned long long acc[4][4];

#pragma unroll 1
    for (int t = 0; t < Tt; t++) {
        // ---- gate i (cols [0,256)) ----
        gate_pass(0 * 128 + tu, t, rbase, Wr2, Wk2, b2, h_sh, x_sh, acc);
#pragma unroll
        for (int r = 0; r < 4; r++)
#pragma unroll
            for (int p = 0; p < 4; p++) {
                float z0, z1; unpack2(acc[r][p], z0, z1);
                gv[r][2 * p]     = sigmoidf_(z0);
                gv[r][2 * p + 1] = sigmoidf_(z1);
            }

        // ---- gate g (cols [512,768)) : P = i * tanh(z_g) ----
        gate_pass(2 * 128 + tu, t, rbase, Wr2, Wk2, b2, h_sh, x_sh, acc);
#pragma unroll
        for (int r = 0; r < 4; r++)
#pragma unroll
            for (int p = 0; p < 4; p++) {
                float z0, z1; unpack2(acc[r][p], z0, z1);
                gv[r][2 * p]     *= tanhf(z0);
                gv[r][2 * p + 1] *= tanhf(z1);
            }

        // ---- gate f (cols [256,512)) : c = sigmoid(z_f)*c + P ----
        gate_pass(1 * 128 + tu, t, rbase, Wr2, Wk2, b2, h_sh, x_sh, acc);
#pragma unroll
        for (int r = 0; r < 4; r++)
#pragma unroll
            for (int p = 0; p < 4; p++) {
                float z0, z1; unpack2(acc[r][p], z0, z1);
                creg[r][2 * p]     = sigmoidf_(z0) * creg[r][2 * p]     + gv[r][2 * p];
                creg[r][2 * p + 1] = sigmoidf_(z1) * creg[r][2 * p + 1] + gv[r][2 * p + 1];
            }

        // ---- gate o (cols [768,1024)) : h = sigmoid(z_o)*tanh(c) ----
        gate_pass(3 * 128 + tu, t, rbase, Wr2, Wk2, b2, h_sh, x_sh, acc);
#pragma unroll
        for (int r = 0; r < 4; r++)
#pragma unroll
            for (int p = 0; p < 4; p++) {
                float z0, z1; unpack2(acc[r][p], z0, z1);
                gv[r][2 * p]     = sigmoidf_(z0) * tanhf(creg[r][2 * p]);
                gv[r][2 * p + 1] = sigmoidf_(z1) * tanhf(creg[r][2 * p + 1]);
            }

        // All reads of h_sh for this step are done before anyone overwrites it.
        __syncthreads();

#pragma unroll
        for (int r = 0; r < 4; r++) {
            float2* hrow = reinterpret_cast<float2*>(&h_sh[rbase + r][0]);
#pragma unroll
            for (int p = 0; p < 4; p++) {
                int u2 = tu + 32 * p;                 // float2 unit index
                float2 hv = make_float2(gv[r][2 * p], gv[r][2 * p + 1]);
                hrow[u2] = hv;
                out2[((size_t)(row0 + rbase + r) * Tt + t) * 128 + u2] = hv;
            }
        }
        __syncthreads();
    }
}

// ---------------------------------------------------------------------------
// Harness entry point
// ---------------------------------------------------------------------------
extern "C" void kernel_launch(void* const* d_in, const int* in_sizes, int n_in,
                              void* d_out, int out_size) {
    const float* x  = (const float*)d_in[0];  // [B,T,F]
    const float* h0 = (const float*)d_in[1];  // [B,U]
    const float* c0 = (const float*)d_in[2];  // [B,U]
    const float* Wk = (const float*)d_in[3];  // [F,4U]
    const float* Wr = (const float*)d_in[4];  // [U,4U]
    const float* b  = (const float*)d_in[5];  // [4U]
    float* out = (float*)d_out;               // [B,T,U]

    lstm_kernel<<<Bsz / BM, NTHREADS>>>(x, h0, c0, Wk, Wr, b, out);
}

// round 2
// speedup vs baseline: 1.5115x; 1.5115x over previous
#include <cuda_runtime.h>
#include <math.h>

typedef unsigned long long ull;

// Problem constants
#define Bsz   32768
#define Tt    7
#define Ff    36
#define Uu    256
#define BM    32      // batch rows per CTA
#define NT    128     // 4 warps
#define RR    8       // rows per thread (per warp: 8 rows; 4 warps * 8 = 32)

// ---------------------------------------------------------------------------
// f32x2 packed-FMA helpers
// ---------------------------------------------------------------------------
__device__ __forceinline__ ull dup2(float a) {
    ull r; asm("mov.b64 %0, {%1, %1};" : "=l"(r) : "f"(a)); return r;
}
__device__ __forceinline__ void unpk(ull v, float& a, float& b) {
    asm("mov.b64 {%0, %1}, %2;" : "=f"(a), "=f"(b) : "l"(v));
}
__device__ __forceinline__ void ffma2(ull& d, ull a, ull b) {
    asm("fma.rn.f32x2 %0, %1, %2, %0;" : "+l"(d) : "l"(a), "l"(b));
}
__device__ __forceinline__ float sgm(float z) { return 1.0f / (1.0f + expf(-z)); }

// ---------------------------------------------------------------------------
// One gate pass: acc[r][j] (f32x2) = b + h @ Wr[:,gate] + x_t @ Wk[:,gate]
// Column mapping for thread lane tu:
//   j=0 -> cols 4*tu+{0,1}, j=1 -> 4*tu+{2,3},
//   j=2 -> 4*(tu+32)+{0,1}, j=3 -> 4*(tu+32)+{2,3}   (cols within the gate)
// ---------------------------------------------------------------------------
__device__ __forceinline__ void gate_pass(
    int gsel, int t, int rbase, int tu,
    const ulonglong2* __restrict__ Wr2,   // Wr viewed as [256][256] ulonglong2
    const ulonglong2* __restrict__ Wk2,   // Wk viewed as [36][256]  ulonglong2
    const ulonglong2* __restrict__ b2,    // b  viewed as [256]      ulonglong2
    const float (*__restrict__ h_sh)[Uu],
    const float (*__restrict__ x_sh)[Tt * Ff],
    ull acc[RR][4])
{
    const int base = gsel * 64 + tu;

    ulonglong2 ba = b2[base];
    ulonglong2 bb = b2[base + 32];
#pragma unroll
    for (int r = 0; r < RR; r++) {
        acc[r][0] = ba.x; acc[r][1] = ba.y;
        acc[r][2] = bb.x; acc[r][3] = bb.y;
    }

    // ---- recurrent term: K = 256 over h ----
    const ulonglong2* wp = Wr2 + base;
#pragma unroll 1
    for (int k = 0; k < Uu; k += 4) {
        float4 h4[RR];
#pragma unroll
        for (int r = 0; r < RR; r++)
            h4[r] = *reinterpret_cast<const float4*>(&h_sh[rbase + r][k]);
#pragma unroll
        for (int kk = 0; kk < 4; kk++) {
            ulonglong2 wa = wp[(k + kk) * 256];
            ulonglong2 wb = wp[(k + kk) * 256 + 32];
#pragma unroll
            for (int r = 0; r < RR; r++) {
                float hv = reinterpret_cast<const float*>(&h4[r])[kk];
                ull h2 = dup2(hv);
                ffma2(acc[r][0], h2, wa.x);
                ffma2(acc[r][1], h2, wa.y);
                ffma2(acc[r][2], h2, wb.x);
                ffma2(acc[r][3], h2, wb.y);
            }
        }
    }

    // ---- input term: K = 36 over x_t (36 = 9 * 4) ----
    const ulonglong2* kp = Wk2 + base;
    const int xoff = t * Ff;
#pragma unroll 1
    for (int k = 0; k < Ff; k += 4) {
        float4 x4[RR];
#pragma unroll
        for (int r = 0; r < RR; r++)
            x4[r] = *reinterpret_cast<const float4*>(&x_sh[rbase + r][xoff + k]);
#pragma unroll
        for (int kk = 0; kk < 4; kk++) {
            ulonglong2 wa = kp[(k + kk) * 256];
            ulonglong2 wb = kp[(k + kk) * 256 + 32];
#pragma unroll
            for (int r = 0; r < RR; r++) {
                float xv = reinterpret_cast<const float*>(&x4[r])[kk];
                ull x2v = dup2(xv);
                ffma2(acc[r][0], x2v, wa.x);
                ffma2(acc[r][1], x2v, wa.y);
                ffma2(acc[r][2], x2v, wb.x);
                ffma2(acc[r][3], x2v, wb.y);
            }
        }
    }
}

// ---------------------------------------------------------------------------
// LSTM kernel: one CTA = 32 batch rows; 2 CTAs co-resident per SM.
// ---------------------------------------------------------------------------
__global__ void __launch_bounds__(NT, 2)
lstm_kernel(const float* __restrict__ x,   // [B,T,F]
            const float* __restrict__ h0,  // [B,U]
            const float* __restrict__ c0,  // [B,U]
            const float* __restrict__ Wk,  // [F,4U]
            const float* __restrict__ Wr,  // [U,4U]
            const float* __restrict__ b,   // [4U]
            float* __restrict__ out)       // [B,T,U]
{
    __shared__ float h_sh[BM][Uu];        // 32 KB
    __shared__ float x_sh[BM][Tt * Ff];   // 31.5 KB
    __shared__ float c_sh[BM][Uu];        // 32 KB

    const int tid   = threadIdx.x;
    const int tu    = tid & 31;
    const int w     = tid >> 5;
    const int rbase = w * RR;
    const int row0  = blockIdx.x * BM;

    // ---- stage h0, c0, x tile into shared (float4 coalesced) ----
    {
        const float4* hsrc = reinterpret_cast<const float4*>(h0 + (size_t)row0 * Uu);
        const float4* csrc = reinterpret_cast<const float4*>(c0 + (size_t)row0 * Uu);
        float4* hdst = reinterpret_cast<float4*>(&h_sh[0][0]);
        float4* cdst = reinterpret_cast<float4*>(&c_sh[0][0]);
#pragma unroll 1
        for (int i = tid; i < BM * Uu / 4; i += NT) {
            hdst[i] = hsrc[i];
            cdst[i] = csrc[i];
        }
        const float4* xsrc = reinterpret_cast<const float4*>(x + (size_t)row0 * (Tt * Ff));
        float4* xdst = reinterpret_cast<float4*>(&x_sh[0][0]);
#pragma unroll 1
        for (int i = tid; i < BM * Tt * Ff / 4; i += NT)
            xdst[i] = xsrc[i];
    }
    __syncthreads();

    const ulonglong2* __restrict__ Wr2 = reinterpret_cast<const ulonglong2*>(Wr);
    const ulonglong2* __restrict__ Wk2 = reinterpret_cast<const ulonglong2*>(Wk);
    const ulonglong2* __restrict__ b2  = reinterpret_cast<const ulonglong2*>(b);
    float4* __restrict__ out4 = reinterpret_cast<float4*>(out);

    float gv[RR][8];      // per-thread gate scratch: tanh(g) -> i*g -> tanh(c) -> h
    ull acc[RR][4];

#pragma unroll 1
    for (int t = 0; t < Tt; t++) {
        // ---- gate g (gsel=2): gv = tanh(z_g) ----
        gate_pass(2, t, rbase, tu, Wr2, Wk2, b2, h_sh, x_sh, acc);
#pragma unroll
        for (int r = 0; r < RR; r++)
#pragma unroll
            for (int j = 0; j < 4; j++) {
                float z0, z1; unpk(acc[r][j], z0, z1);
                gv[r][2 * j]     = tanhf(z0);
                gv[r][2 * j + 1] = tanhf(z1);
            }

        // ---- gate i (gsel=0): gv = sigmoid(z_i) * gv ----
        gate_pass(0, t, rbase, tu, Wr2, Wk2, b2, h_sh, x_sh, acc);
#pragma unroll
        for (int r = 0; r < RR; r++)
#pragma unroll
            for (int j = 0; j < 4; j++) {
                float z0, z1; unpk(acc[r][j], z0, z1);
                gv[r][2 * j]     *= sgm(z0);
                gv[r][2 * j + 1] *= sgm(z1);
            }

        // ---- gate f (gsel=1): c = sigmoid(z_f)*c + gv ; gv = tanh(c) ----
        gate_pass(1, t, rbase, tu, Wr2, Wk2, b2, h_sh, x_sh, acc);
#pragma unroll
        for (int r = 0; r < RR; r++) {
            const int rr = rbase + r;
            float4 cA = *reinterpret_cast<float4*>(&c_sh[rr][4 * tu]);
            float4 cB = *reinterpret_cast<float4*>(&c_sh[rr][4 * (tu + 32)]);
            float z0, z1;
            unpk(acc[r][0], z0, z1);
            cA.x = sgm(z0) * cA.x + gv[r][0];
            cA.y = sgm(z1) * cA.y + gv[r][1];
            unpk(acc[r][1], z0, z1);
            cA.z = sgm(z0) * cA.z + gv[r][2];
            cA.w = sgm(z1) * cA.w + gv[r][3];
            unpk(acc[r][2], z0, z1);
            cB.x = sgm(z0) * cB.x + gv[r][4];
            cB.y = sgm(z1) * cB.y + gv[r][5];
            unpk(acc[r][3], z0, z1);
            cB.z = sgm(z0) * cB.z + gv[r][6];
            cB.w = sgm(z1) * cB.w + gv[r][7];
            *reinterpret_cast<float4*>(&c_sh[rr][4 * tu])        = cA;
            *reinterpret_cast<float4*>(&c_sh[rr][4 * (tu + 32)]) = cB;
            gv[r][0] = tanhf(cA.x); gv[r][1] = tanhf(cA.y);
            gv[r][2] = tanhf(cA.z); gv[r][3] = tanhf(cA.w);
            gv[r][4] = tanhf(cB.x); gv[r][5] = tanhf(cB.y);
            gv[r][6] = tanhf(cB.z); gv[r][7] = tanhf(cB.w);
        }

        // ---- gate o (gsel=3): h = sigmoid(z_o) * gv ----
        gate_pass(3, t, rbase, tu, Wr2, Wk2, b2, h_sh, x_sh, acc);
#pragma unroll
        for (int r = 0; r < RR; r++)
#pragma unroll
            for (int j = 0; j < 4; j++) {
                float z0, z1; unpk(acc[r][j], z0, z1);
                gv[r][2 * j]     *= sgm(z0);
                gv[r][2 * j + 1] *= sgm(z1);
            }

        // All h_sh reads for this step are done; now publish h_new.
        __syncthreads();
#pragma unroll
        for (int r = 0; r < RR; r++) {
            const int rr = rbase + r;
            float4 hA = make_float4(gv[r][0], gv[r][1], gv[r][2], gv[r][3]);
            float4 hB = make_float4(gv[r][4], gv[r][5], gv[r][6], gv[r][7]);
            *reinterpret_cast<float4*>(&h_sh[rr][4 * tu])        = hA;
            *reinterpret_cast<float4*>(&h_sh[rr][4 * (tu + 32)]) = hB;
            size_t ob = ((size_t)(row0 + rr) * Tt + t) * 64;   // float4 units per [row,t]
            out4[ob + tu]      = hA;
            out4[ob + tu + 32] = hB;
        }
        __syncthreads();
    }
}

// ---------------------------------------------------------------------------
// Harness entry point
// ---------------------------------------------------------------------------
extern "C" void kernel_launch(void* const* d_in, const int* in_sizes, int n_in,
                              void* d_out, int out_size) {
    const float* x  = (const float*)d_in[0];  // [B,T,F]
    const float* h0 = (const float*)d_in[1];  // [B,U]
    const float* c0 = (const float*)d_in[2];  // [B,U]
    const float* Wk = (const float*)d_in[3];  // [F,4U]
    const float* Wr = (const float*)d_in[4];  // [U,4U]
    const float* b  = (const float*)d_in[5];  // [4U]
    float* out = (float*)d_out;               // [B,T,U]

    lstm_kernel<<<Bsz / BM, NT>>>(x, h0, c0, Wk, Wr, b, out);
}